// round 1
// baseline (speedup 1.0000x reference)
#include <cuda_runtime.h>

#define N_NODES 50000
#define N_EDGES 800000
#define FEAT 96
#define HID_H 64
#define HID 128
#define NGROUPS (N_EDGES / 4)
#define INIT_ENC 0x007FFFFFu  /* enc(-inf) */

// ---------------- scratch (device globals; no allocs allowed) ----------------
__device__ float    g_delta[N_NODES * 3];
__device__ float    g_xa[N_NODES * HID];
__device__ unsigned g_agg[N_NODES * FEAT];

// Order-preserving float <-> unsigned encoding for atomicMax-based segment_max
__device__ __forceinline__ unsigned enc_f(float f) {
    unsigned u = __float_as_uint(f);
    return (u & 0x80000000u) ? ~u : (u | 0x80000000u);
}
__device__ __forceinline__ float dec_f(unsigned k) {
    unsigned u = (k & 0x80000000u) ? (k & 0x7FFFFFFFu) : ~k;
    return __uint_as_float(u);
}

// ---------------- kernel 0: init agg to enc(-inf) ----------------
__global__ void init_agg_kernel() {
    int i = blockIdx.x * blockDim.x + threadIdx.x;
    int stride = gridDim.x * blockDim.x;
    for (; i < N_NODES * FEAT; i += stride) g_agg[i] = INIT_ENC;
}

// ---------------- kernel 1: delta = mlp_h(x);  xa = x @ f_w0[3:] + f_b0 ----------------
__global__ __launch_bounds__(256) void node_pre_kernel(
    const float* __restrict__ x,
    const float* __restrict__ h_w0, const float* __restrict__ h_b0,
    const float* __restrict__ h_w1, const float* __restrict__ h_b1,
    const float* __restrict__ f_w0, const float* __restrict__ f_b0)
{
    extern __shared__ float sm[];
    float* s_hw0 = sm;                       // 96*64
    float* s_fw0 = s_hw0 + FEAT * HID_H;     // 96*128 (rows 3..98 of f_w0)
    float* s_hw1 = s_fw0 + FEAT * HID;       // 64*3
    float* s_hb0 = s_hw1 + HID_H * 3;        // 64
    float* s_hb1 = s_hb0 + HID_H;            // 3 (pad 1)
    float* s_fb0 = s_hb1 + 4;                // 128
    float* s_x   = s_fb0 + HID;              // 8*96
    float* s_hh  = s_x + 8 * FEAT;           // 8*64

    int tid = threadIdx.x;
    for (int i = tid; i < FEAT * HID_H; i += 256) s_hw0[i] = h_w0[i];
    for (int i = tid; i < FEAT * HID;   i += 256) s_fw0[i] = f_w0[3 * HID + i];
    for (int i = tid; i < HID_H * 3;    i += 256) s_hw1[i] = h_w1[i];
    if (tid < HID_H) s_hb0[tid] = h_b0[tid];
    if (tid < 3)     s_hb1[tid] = h_b1[tid];
    if (tid < HID)   s_fb0[tid] = f_b0[tid];
    __syncthreads();

    int warp = tid >> 5, lane = tid & 31;
    int warps_total = gridDim.x * 8;
    float* sx = s_x + warp * FEAT;
    float* sh = s_hh + warp * HID_H;

    for (int node = blockIdx.x * 8 + warp; node < N_NODES; node += warps_total) {
        const float* xr = x + (long)node * FEAT;
        sx[lane]      = xr[lane];
        sx[lane + 32] = xr[lane + 32];
        sx[lane + 64] = xr[lane + 64];
        __syncwarp();

        // mlp_h hidden (64)
        float a0 = s_hb0[lane], a1 = s_hb0[lane + 32];
        #pragma unroll 8
        for (int k = 0; k < FEAT; k++) {
            float xv = sx[k];
            a0 = fmaf(xv, s_hw0[k * HID_H + lane], a0);
            a1 = fmaf(xv, s_hw0[k * HID_H + lane + 32], a1);
        }
        sh[lane]      = fmaxf(a0, 0.f);
        sh[lane + 32] = fmaxf(a1, 0.f);
        __syncwarp();

        if (lane < 3) {
            float d = s_hb1[lane];
            #pragma unroll 8
            for (int j = 0; j < HID_H; j++) d = fmaf(sh[j], s_hw1[j * 3 + lane], d);
            g_delta[node * 3 + lane] = d;
        }

        // xa (128), NO relu (relu happens after adding rel contribution per-edge)
        float b0v = s_fb0[lane], b1v = s_fb0[lane + 32],
              b2v = s_fb0[lane + 64], b3v = s_fb0[lane + 96];
        #pragma unroll 8
        for (int k = 0; k < FEAT; k++) {
            float xv = sx[k];
            const float* w = s_fw0 + k * HID;
            b0v = fmaf(xv, w[lane], b0v);
            b1v = fmaf(xv, w[lane + 32], b1v);
            b2v = fmaf(xv, w[lane + 64], b2v);
            b3v = fmaf(xv, w[lane + 96], b3v);
        }
        float* xo = g_xa + (long)node * HID;
        xo[lane] = b0v; xo[lane + 32] = b1v; xo[lane + 64] = b2v; xo[lane + 96] = b3v;
        __syncwarp();
    }
}

// ---------------- kernel 2: per-edge MLP + atomic segment max ----------------
// warp processes 4 edges per pass. h staged transposed [j][edge] for float4 broadcast.
__global__ __launch_bounds__(256) void edge_kernel(
    const float* __restrict__ pos,
    const int*   __restrict__ ei,      // [2, E] int32
    const float* __restrict__ f_w0,    // rows 0..2 used
    const float* __restrict__ f_w1,
    const float* __restrict__ f_b1)
{
    extern __shared__ float sm[];
    float* s_w3 = sm;                  // 3*128
    float* s_w1 = s_w3 + 3 * HID;      // 128*96
    float* s_b1 = s_w1 + HID * FEAT;   // 96
    float* s_h  = s_b1 + FEAT;         // 8 warps * 128 * 4  (16B aligned: offset 12768 floats)

    int tid = threadIdx.x;
    for (int i = tid; i < 3 * HID; i += 256)     s_w3[i] = f_w0[i];
    for (int i = tid; i < HID * FEAT; i += 256)  s_w1[i] = f_w1[i];
    if (tid < FEAT) s_b1[tid] = f_b1[tid];
    __syncthreads();

    int warp = tid >> 5, lane = tid & 31;
    float* hw = s_h + warp * (HID * 4);

    for (int g = blockIdx.x * 8 + warp; g < NGROUPS; g += gridDim.x * 8) {
        int src[4], dst[4];
        float rel[4][3];
        #pragma unroll
        for (int e = 0; e < 4; e++) {
            int s = ei[4 * g + e];
            int d = ei[N_EDGES + 4 * g + e];
            src[e] = s; dst[e] = d;
            #pragma unroll
            for (int c = 0; c < 3; c++)
                rel[e][c] = pos[s * 3 + c] - pos[d * 3 + c] + g_delta[d * 3 + c];
        }

        // phase 1: h[j][e] = relu(rel_e . W3[:,j] + xa[src_e][j])
        #pragma unroll
        for (int i = 0; i < 4; i++) {
            int j = lane + 32 * i;
            float w30 = s_w3[j], w31 = s_w3[HID + j], w32 = s_w3[2 * HID + j];
            float4 hv;
            float h;
            h = g_xa[(long)src[0] * HID + j];
            hv.x = fmaxf(fmaf(rel[0][0], w30, fmaf(rel[0][1], w31, fmaf(rel[0][2], w32, h))), 0.f);
            h = g_xa[(long)src[1] * HID + j];
            hv.y = fmaxf(fmaf(rel[1][0], w30, fmaf(rel[1][1], w31, fmaf(rel[1][2], w32, h))), 0.f);
            h = g_xa[(long)src[2] * HID + j];
            hv.z = fmaxf(fmaf(rel[2][0], w30, fmaf(rel[2][1], w31, fmaf(rel[2][2], w32, h))), 0.f);
            h = g_xa[(long)src[3] * HID + j];
            hv.w = fmaxf(fmaf(rel[3][0], w30, fmaf(rel[3][1], w31, fmaf(rel[3][2], w32, h))), 0.f);
            *reinterpret_cast<float4*>(&hw[j * 4]) = hv;
        }
        __syncwarp();

        // phase 2: e[edge][c] = b1[c] + sum_j h[edge][j] * W1[j][c],  c in {lane, lane+32, lane+64}
        float acc[4][3];
        #pragma unroll
        for (int e = 0; e < 4; e++) {
            acc[e][0] = s_b1[lane];
            acc[e][1] = s_b1[lane + 32];
            acc[e][2] = s_b1[lane + 64];
        }
        #pragma unroll 8
        for (int j = 0; j < HID; j++) {
            float4 hv = *reinterpret_cast<const float4*>(&hw[j * 4]);  // broadcast
            const float* w = s_w1 + j * FEAT;
            float w0 = w[lane], w1 = w[lane + 32], w2 = w[lane + 64];
            acc[0][0] = fmaf(hv.x, w0, acc[0][0]);
            acc[0][1] = fmaf(hv.x, w1, acc[0][1]);
            acc[0][2] = fmaf(hv.x, w2, acc[0][2]);
            acc[1][0] = fmaf(hv.y, w0, acc[1][0]);
            acc[1][1] = fmaf(hv.y, w1, acc[1][1]);
            acc[1][2] = fmaf(hv.y, w2, acc[1][2]);
            acc[2][0] = fmaf(hv.z, w0, acc[2][0]);
            acc[2][1] = fmaf(hv.z, w1, acc[2][1]);
            acc[2][2] = fmaf(hv.z, w2, acc[2][2]);
            acc[3][0] = fmaf(hv.w, w0, acc[3][0]);
            acc[3][1] = fmaf(hv.w, w1, acc[3][1]);
            acc[3][2] = fmaf(hv.w, w2, acc[3][2]);
        }
        #pragma unroll
        for (int e = 0; e < 4; e++) {
            unsigned* base = g_agg + (long)dst[e] * FEAT;
            atomicMax(base + lane,      enc_f(acc[e][0]));
            atomicMax(base + lane + 32, enc_f(acc[e][1]));
            atomicMax(base + lane + 64, enc_f(acc[e][2]));
        }
        __syncwarp();
    }
}

// ---------------- kernel 3: out = x + mlp_g(decode(agg)) ----------------
__global__ __launch_bounds__(256) void node_post_kernel(
    const float* __restrict__ x,
    const float* __restrict__ g_w0, const float* __restrict__ g_b0,
    const float* __restrict__ g_w1, const float* __restrict__ g_b1,
    float* __restrict__ out)
{
    extern __shared__ float sm[];
    float* s_gw0 = sm;                     // 96*128
    float* s_gw1 = s_gw0 + FEAT * HID;     // 128*96
    float* s_gb0 = s_gw1 + HID * FEAT;     // 128
    float* s_gb1 = s_gb0 + HID;            // 96
    float* s_ag  = s_gb1 + FEAT;           // 8*96
    float* s_h   = s_ag + 8 * FEAT;        // 8*128

    int tid = threadIdx.x;
    for (int i = tid; i < FEAT * HID; i += 256) s_gw0[i] = g_w0[i];
    for (int i = tid; i < HID * FEAT; i += 256) s_gw1[i] = g_w1[i];
    if (tid < HID)  s_gb0[tid] = g_b0[tid];
    if (tid < FEAT) s_gb1[tid] = g_b1[tid];
    __syncthreads();

    int warp = tid >> 5, lane = tid & 31;
    int warps_total = gridDim.x * 8;
    float* ag = s_ag + warp * FEAT;
    float* hh = s_h + warp * HID;

    for (int node = blockIdx.x * 8 + warp; node < N_NODES; node += warps_total) {
        const unsigned* ab = g_agg + (long)node * FEAT;
        #pragma unroll
        for (int i = 0; i < 3; i++) {
            unsigned k = ab[lane + 32 * i];
            ag[lane + 32 * i] = (k == INIT_ENC) ? 0.f : dec_f(k);
        }
        __syncwarp();

        float a0 = s_gb0[lane], a1 = s_gb0[lane + 32],
              a2 = s_gb0[lane + 64], a3 = s_gb0[lane + 96];
        #pragma unroll 8
        for (int k = 0; k < FEAT; k++) {
            float v = ag[k];
            const float* w = s_gw0 + k * HID;
            a0 = fmaf(v, w[lane], a0);
            a1 = fmaf(v, w[lane + 32], a1);
            a2 = fmaf(v, w[lane + 64], a2);
            a3 = fmaf(v, w[lane + 96], a3);
        }
        hh[lane]      = fmaxf(a0, 0.f);
        hh[lane + 32] = fmaxf(a1, 0.f);
        hh[lane + 64] = fmaxf(a2, 0.f);
        hh[lane + 96] = fmaxf(a3, 0.f);
        __syncwarp();

        float o0 = s_gb1[lane], o1 = s_gb1[lane + 32], o2 = s_gb1[lane + 64];
        #pragma unroll 8
        for (int j = 0; j < HID; j++) {
            float hv = hh[j];
            const float* w = s_gw1 + j * FEAT;
            o0 = fmaf(hv, w[lane], o0);
            o1 = fmaf(hv, w[lane + 32], o1);
            o2 = fmaf(hv, w[lane + 64], o2);
        }
        const float* xr = x + (long)node * FEAT;
        float* orow = out + (long)node * FEAT;
        orow[lane]      = xr[lane]      + o0;
        orow[lane + 32] = xr[lane + 32] + o1;
        orow[lane + 64] = xr[lane + 64] + o2;
        __syncwarp();
    }
}

// ---------------- launch ----------------
extern "C" void kernel_launch(void* const* d_in, const int* in_sizes, int n_in,
                              void* d_out, int out_size)
{
    const float* x    = (const float*)d_in[0];
    const float* pos  = (const float*)d_in[1];
    const int*   ei   = (const int*)  d_in[2];
    const float* h_w0 = (const float*)d_in[3];
    const float* h_b0 = (const float*)d_in[4];
    const float* h_w1 = (const float*)d_in[5];
    const float* h_b1 = (const float*)d_in[6];
    const float* f_w0 = (const float*)d_in[7];
    const float* f_b0 = (const float*)d_in[8];
    const float* f_w1 = (const float*)d_in[9];
    const float* f_b1 = (const float*)d_in[10];
    const float* g_w0 = (const float*)d_in[11];
    const float* g_b0 = (const float*)d_in[12];
    const float* g_w1 = (const float*)d_in[13];
    const float* g_b1 = (const float*)d_in[14];
    float* out = (float*)d_out;

    const int smem_pre  = (FEAT*HID_H + FEAT*HID + HID_H*3 + HID_H + 4 + HID + 8*FEAT + 8*HID_H) * 4;
    const int smem_edge = (3*HID + HID*FEAT + FEAT + 8*HID*4) * 4;
    const int smem_post = (FEAT*HID + HID*FEAT + HID + FEAT + 8*FEAT + 8*HID) * 4;

    cudaFuncSetAttribute(node_pre_kernel,  cudaFuncAttributeMaxDynamicSharedMemorySize, smem_pre);
    cudaFuncSetAttribute(edge_kernel,      cudaFuncAttributeMaxDynamicSharedMemorySize, smem_edge);
    cudaFuncSetAttribute(node_post_kernel, cudaFuncAttributeMaxDynamicSharedMemorySize, smem_post);

    init_agg_kernel<<<296, 256>>>();
    node_pre_kernel<<<296, 256, smem_pre>>>(x, h_w0, h_b0, h_w1, h_b1, f_w0, f_b0);
    edge_kernel<<<444, 256, smem_edge>>>(pos, ei, f_w0, f_w1, f_b1);
    node_post_kernel<<<296, 256, smem_post>>>(x, g_w0, g_b0, g_w1, g_b1, out);
}

// round 2
// speedup vs baseline: 1.3050x; 1.3050x over previous
#include <cuda_runtime.h>

#define N_NODES 50000
#define N_EDGES 800000
#define FEAT 96
#define HID_H 64
#define HID 128
#define EPG 8                       /* edges per warp pass */
#define NGROUPS (N_EDGES / EPG)     /* 100000 */
#define INIT_ENC 0x007FFFFFu        /* enc(-inf) */

typedef unsigned long long u64;

// ---------------- scratch (device globals; no allocs allowed) ----------------
__device__ float    g_delta[N_NODES * 3];
__device__ float    g_xa[N_NODES * HID];
__device__ unsigned g_agg[N_NODES * FEAT];

// Order-preserving float <-> unsigned encoding for atomicMax-based segment_max
__device__ __forceinline__ unsigned enc_f(float f) {
    unsigned u = __float_as_uint(f);
    return (u & 0x80000000u) ? ~u : (u | 0x80000000u);
}
__device__ __forceinline__ float dec_f(unsigned k) {
    unsigned u = (k & 0x80000000u) ? (k & 0x7FFFFFFFu) : ~k;
    return __uint_as_float(u);
}

// ---- packed f32x2 helpers (FFMA2: ptxas never auto-fuses; PTX-only) ----
__device__ __forceinline__ u64 pack2(float a, float b) {
    u64 r; asm("mov.b64 %0, {%1, %2};" : "=l"(r) : "f"(a), "f"(b)); return r;
}
__device__ __forceinline__ u64 dup2(float a) {
    u64 r; asm("mov.b64 %0, {%1, %1};" : "=l"(r) : "f"(a)); return r;
}
__device__ __forceinline__ void unpack2(u64 v, float& a, float& b) {
    asm("mov.b64 {%0, %1}, %2;" : "=f"(a), "=f"(b) : "l"(v));
}
__device__ __forceinline__ void fma2(u64& acc, u64 a, u64 b) {
    asm("fma.rn.f32x2 %0, %1, %2, %0;" : "+l"(acc) : "l"(a), "l"(b));
}

// ---------------- kernel 0: init agg to enc(-inf) ----------------
__global__ void init_agg_kernel() {
    int i = blockIdx.x * blockDim.x + threadIdx.x;
    int stride = gridDim.x * blockDim.x;
    for (; i < N_NODES * FEAT; i += stride) g_agg[i] = INIT_ENC;
}

// ---------------- kernel 1: delta = mlp_h(x);  xa = x @ f_w0[3:] + f_b0 ----------------
// 4 nodes per warp pass; x staged transposed [k][node4] for float4 broadcast; f32x2 FMA.
__global__ __launch_bounds__(256, 2) void node_pre_kernel(
    const float* __restrict__ x,
    const float* __restrict__ h_w0, const float* __restrict__ h_b0,
    const float* __restrict__ h_w1, const float* __restrict__ h_b1,
    const float* __restrict__ f_w0, const float* __restrict__ f_b0)
{
    extern __shared__ float sm[];
    float* s_hw0 = sm;                       // 96*64
    float* s_fw0 = s_hw0 + FEAT * HID_H;     // 96*128 (rows 3..98 of f_w0)
    float* s_hw1 = s_fw0 + FEAT * HID;       // 64*3
    float* s_hb0 = s_hw1 + HID_H * 3;        // 64
    float* s_hb1 = s_hb0 + HID_H;            // 4 (3 + pad)
    float* s_fb0 = s_hb1 + 4;                // 128
    float* s_x4  = s_fb0 + HID;              // 8 warps * 96*4
    float* s_h4  = s_x4 + 8 * FEAT * 4;      // 8 warps * 64*4

    int tid = threadIdx.x;
    for (int i = tid; i < FEAT * HID_H; i += 256) s_hw0[i] = h_w0[i];
    for (int i = tid; i < FEAT * HID;   i += 256) s_fw0[i] = f_w0[3 * HID + i];
    for (int i = tid; i < HID_H * 3;    i += 256) s_hw1[i] = h_w1[i];
    if (tid < HID_H) s_hb0[tid] = h_b0[tid];
    if (tid < 3)     s_hb1[tid] = h_b1[tid];
    if (tid < HID)   s_fb0[tid] = f_b0[tid];
    __syncthreads();

    int warp = tid >> 5, lane = tid & 31;
    int warps_total = gridDim.x * 8;
    float* x4 = s_x4 + warp * FEAT * 4;
    float* h4 = s_h4 + warp * HID_H * 4;

    for (int nb = (blockIdx.x * 8 + warp) * 4; nb < N_NODES; nb += warps_total * 4) {
        // stage x transposed: x4[k*4 + e]
        #pragma unroll
        for (int e = 0; e < 4; e++) {
            const float* xr = x + (long)(nb + e) * FEAT;
            #pragma unroll
            for (int i = 0; i < 3; i++) {
                int k = lane + 32 * i;
                x4[k * 4 + e] = xr[k];
            }
        }
        __syncwarp();

        // ---- mlp_h hidden (64 outs), nodes packed in pairs ----
        {
            u64 acc[2][2];  // [node-pair][half: j=lane / j=lane+32]
            acc[0][0] = acc[1][0] = dup2(s_hb0[lane]);
            acc[0][1] = acc[1][1] = dup2(s_hb0[lane + 32]);
            #pragma unroll 4
            for (int k = 0; k < FEAT; k++) {
                const ulonglong2* xp = (const ulonglong2*)&x4[k * 4];
                ulonglong2 xv = *xp;                // (n0,n1) (n2,n3)
                u64 w0 = dup2(s_hw0[k * HID_H + lane]);
                u64 w1 = dup2(s_hw0[k * HID_H + lane + 32]);
                fma2(acc[0][0], xv.x, w0);
                fma2(acc[1][0], xv.y, w0);
                fma2(acc[0][1], xv.x, w1);
                fma2(acc[1][1], xv.y, w1);
            }
            // relu + stage transposed h4[j*4+e]
            #pragma unroll
            for (int half = 0; half < 2; half++) {
                int j = lane + 32 * half;
                float a, b, c, d;
                unpack2(acc[0][half], a, b);
                unpack2(acc[1][half], c, d);
                float4 hv = make_float4(fmaxf(a, 0.f), fmaxf(b, 0.f),
                                        fmaxf(c, 0.f), fmaxf(d, 0.f));
                *reinterpret_cast<float4*>(&h4[j * 4]) = hv;
            }
        }
        __syncwarp();

        // ---- delta = h @ h_w1 + h_b1 (lanes 0..11: e=lane/3, c=lane%3) ----
        if (lane < 12) {
            int e = lane / 3, c = lane % 3;
            float d = s_hb1[c];
            #pragma unroll 8
            for (int j = 0; j < HID_H; j++)
                d = fmaf(h4[j * 4 + e], s_hw1[j * 3 + c], d);
            g_delta[(nb + e) * 3 + c] = d;
        }

        // ---- xa (128 outs, no relu) ----
        {
            u64 acc[2][4];  // [node-pair][quarter]
            #pragma unroll
            for (int q = 0; q < 4; q++)
                acc[0][q] = acc[1][q] = dup2(s_fb0[lane + 32 * q]);
            #pragma unroll 4
            for (int k = 0; k < FEAT; k++) {
                const ulonglong2* xp = (const ulonglong2*)&x4[k * 4];
                ulonglong2 xv = *xp;
                const float* w = s_fw0 + k * HID;
                #pragma unroll
                for (int q = 0; q < 4; q++) {
                    u64 wq = dup2(w[lane + 32 * q]);
                    fma2(acc[0][q], xv.x, wq);
                    fma2(acc[1][q], xv.y, wq);
                }
            }
            #pragma unroll
            for (int q = 0; q < 4; q++) {
                float v0, v1, v2, v3;
                unpack2(acc[0][q], v0, v1);
                unpack2(acc[1][q], v2, v3);
                int col = lane + 32 * q;
                g_xa[(long)(nb + 0) * HID + col] = v0;
                g_xa[(long)(nb + 1) * HID + col] = v1;
                g_xa[(long)(nb + 2) * HID + col] = v2;
                g_xa[(long)(nb + 3) * HID + col] = v3;
            }
        }
        __syncwarp();
    }
}

// ---------------- kernel 2: per-edge MLP + atomic segment max ----------------
// 8 edges per warp pass; h staged transposed [j][edge8]; f32x2 packed FMA in phase 2.
__global__ __launch_bounds__(256, 2) void edge_kernel(
    const float* __restrict__ pos,
    const int*   __restrict__ ei,      // [2, E] int32
    const float* __restrict__ f_w0,    // rows 0..2 used
    const float* __restrict__ f_w1,
    const float* __restrict__ f_b1)
{
    extern __shared__ float sm[];
    float* s_w3 = sm;                  // 3*128
    float* s_w1 = s_w3 + 3 * HID;      // 128*96
    float* s_b1 = s_w1 + HID * FEAT;   // 96
    float* s_h  = s_b1 + FEAT;         // 8 warps * 128 * 8

    int tid = threadIdx.x;
    for (int i = tid; i < 3 * HID; i += 256)     s_w3[i] = f_w0[i];
    for (int i = tid; i < HID * FEAT; i += 256)  s_w1[i] = f_w1[i];
    if (tid < FEAT) s_b1[tid] = f_b1[tid];
    __syncthreads();

    int warp = tid >> 5, lane = tid & 31;
    float* hw = s_h + warp * (HID * EPG);

    for (int g = blockIdx.x * 8 + warp; g < NGROUPS; g += gridDim.x * 8) {
        int src[EPG], dst[EPG];
        float rel[EPG][3];
        #pragma unroll
        for (int e = 0; e < EPG; e++) {
            int s = ei[EPG * g + e];
            int d = ei[N_EDGES + EPG * g + e];
            src[e] = s; dst[e] = d;
            #pragma unroll
            for (int c = 0; c < 3; c++)
                rel[e][c] = pos[s * 3 + c] - pos[d * 3 + c] + g_delta[d * 3 + c];
        }

        // phase 1: h[j][e] = relu(rel_e . W3[:,j] + xa[src_e][j])
        #pragma unroll
        for (int i = 0; i < 4; i++) {
            int j = lane + 32 * i;
            float w30 = s_w3[j], w31 = s_w3[HID + j], w32 = s_w3[2 * HID + j];
            float hv[EPG];
            #pragma unroll
            for (int e = 0; e < EPG; e++) {
                float h = g_xa[(long)src[e] * HID + j];
                hv[e] = fmaxf(fmaf(rel[e][0], w30,
                              fmaf(rel[e][1], w31,
                              fmaf(rel[e][2], w32, h))), 0.f);
            }
            *reinterpret_cast<float4*>(&hw[j * EPG])     = make_float4(hv[0], hv[1], hv[2], hv[3]);
            *reinterpret_cast<float4*>(&hw[j * EPG + 4]) = make_float4(hv[4], hv[5], hv[6], hv[7]);
        }
        __syncwarp();

        // phase 2: e[edge][c] = b1 + sum_j h[edge][j] * W1[j][c]
        // edges packed in pairs: acc[p][c] = (edge 2p, edge 2p+1) for col lane+32c
        u64 acc[4][3];
        #pragma unroll
        for (int c = 0; c < 3; c++) {
            u64 b = dup2(s_b1[lane + 32 * c]);
            acc[0][c] = b; acc[1][c] = b; acc[2][c] = b; acc[3][c] = b;
        }
        #pragma unroll 4
        for (int j = 0; j < HID; j++) {
            const ulonglong2* hp = (const ulonglong2*)&hw[j * EPG];
            ulonglong2 hA = hp[0];   // (e0,e1)(e2,e3)
            ulonglong2 hB = hp[1];   // (e4,e5)(e6,e7)
            const float* w = s_w1 + j * FEAT;
            u64 w0 = dup2(w[lane]);
            u64 w1 = dup2(w[lane + 32]);
            u64 w2 = dup2(w[lane + 64]);
            fma2(acc[0][0], hA.x, w0); fma2(acc[0][1], hA.x, w1); fma2(acc[0][2], hA.x, w2);
            fma2(acc[1][0], hA.y, w0); fma2(acc[1][1], hA.y, w1); fma2(acc[1][2], hA.y, w2);
            fma2(acc[2][0], hB.x, w0); fma2(acc[2][1], hB.x, w1); fma2(acc[2][2], hB.x, w2);
            fma2(acc[3][0], hB.y, w0); fma2(acc[3][1], hB.y, w1); fma2(acc[3][2], hB.y, w2);
        }

        #pragma unroll
        for (int p = 0; p < 4; p++) {
            unsigned* b0 = g_agg + (long)dst[2 * p] * FEAT;
            unsigned* b1 = g_agg + (long)dst[2 * p + 1] * FEAT;
            #pragma unroll
            for (int c = 0; c < 3; c++) {
                float v0, v1;
                unpack2(acc[p][c], v0, v1);
                atomicMax(b0 + lane + 32 * c, enc_f(v0));
                atomicMax(b1 + lane + 32 * c, enc_f(v1));
            }
        }
        __syncwarp();
    }
}

// ---------------- kernel 3: out = x + mlp_g(decode(agg)) ----------------
// 4 nodes per warp pass; agg and h staged transposed; f32x2 packed FMA.
__global__ __launch_bounds__(256) void node_post_kernel(
    const float* __restrict__ x,
    const float* __restrict__ g_w0, const float* __restrict__ g_b0,
    const float* __restrict__ g_w1, const float* __restrict__ g_b1,
    float* __restrict__ out)
{
    extern __shared__ float sm[];
    float* s_gw0 = sm;                     // 96*128
    float* s_gw1 = s_gw0 + FEAT * HID;     // 128*96
    float* s_gb0 = s_gw1 + HID * FEAT;     // 128
    float* s_gb1 = s_gb0 + HID;            // 96
    float* s_ag4 = s_gb1 + FEAT;           // 8 warps * 96*4
    float* s_h4  = s_ag4 + 8 * FEAT * 4;   // 8 warps * 128*4

    int tid = threadIdx.x;
    for (int i = tid; i < FEAT * HID; i += 256) s_gw0[i] = g_w0[i];
    for (int i = tid; i < HID * FEAT; i += 256) s_gw1[i] = g_w1[i];
    if (tid < HID)  s_gb0[tid] = g_b0[tid];
    if (tid < FEAT) s_gb1[tid] = g_b1[tid];
    __syncthreads();

    int warp = tid >> 5, lane = tid & 31;
    int warps_total = gridDim.x * 8;
    float* ag4 = s_ag4 + warp * FEAT * 4;
    float* h4  = s_h4 + warp * HID * 4;

    for (int nb = (blockIdx.x * 8 + warp) * 4; nb < N_NODES; nb += warps_total * 4) {
        // stage decoded agg transposed: ag4[k*4 + e]
        #pragma unroll
        for (int e = 0; e < 4; e++) {
            const unsigned* ab = g_agg + (long)(nb + e) * FEAT;
            #pragma unroll
            for (int i = 0; i < 3; i++) {
                int k = lane + 32 * i;
                unsigned kk = ab[k];
                ag4[k * 4 + e] = (kk == INIT_ENC) ? 0.f : dec_f(kk);
            }
        }
        __syncwarp();

        // ---- hidden layer (128 outs) ----
        u64 acc[2][4];  // [node-pair][quarter]
        #pragma unroll
        for (int q = 0; q < 4; q++)
            acc[0][q] = acc[1][q] = dup2(s_gb0[lane + 32 * q]);
        #pragma unroll 4
        for (int k = 0; k < FEAT; k++) {
            const ulonglong2* ap = (const ulonglong2*)&ag4[k * 4];
            ulonglong2 av = *ap;
            const float* w = s_gw0 + k * HID;
            #pragma unroll
            for (int q = 0; q < 4; q++) {
                u64 wq = dup2(w[lane + 32 * q]);
                fma2(acc[0][q], av.x, wq);
                fma2(acc[1][q], av.y, wq);
            }
        }
        // relu + stage transposed
        #pragma unroll
        for (int q = 0; q < 4; q++) {
            int j = lane + 32 * q;
            float a, b, c, d;
            unpack2(acc[0][q], a, b);
            unpack2(acc[1][q], c, d);
            *reinterpret_cast<float4*>(&h4[j * 4]) =
                make_float4(fmaxf(a, 0.f), fmaxf(b, 0.f), fmaxf(c, 0.f), fmaxf(d, 0.f));
        }
        __syncwarp();

        // ---- output layer (96 outs) ----
        u64 acc2[2][3];
        #pragma unroll
        for (int c = 0; c < 3; c++)
            acc2[0][c] = acc2[1][c] = dup2(s_gb1[lane + 32 * c]);
        #pragma unroll 4
        for (int j = 0; j < HID; j++) {
            const ulonglong2* hp = (const ulonglong2*)&h4[j * 4];
            ulonglong2 hv = *hp;
            const float* w = s_gw1 + j * FEAT;
            #pragma unroll
            for (int c = 0; c < 3; c++) {
                u64 wc = dup2(w[lane + 32 * c]);
                fma2(acc2[0][c], hv.x, wc);
                fma2(acc2[1][c], hv.y, wc);
            }
        }
        #pragma unroll
        for (int c = 0; c < 3; c++) {
            float v0, v1, v2, v3;
            unpack2(acc2[0][c], v0, v1);
            unpack2(acc2[1][c], v2, v3);
            int col = lane + 32 * c;
            out[(long)(nb + 0) * FEAT + col] = x[(long)(nb + 0) * FEAT + col] + v0;
            out[(long)(nb + 1) * FEAT + col] = x[(long)(nb + 1) * FEAT + col] + v1;
            out[(long)(nb + 2) * FEAT + col] = x[(long)(nb + 2) * FEAT + col] + v2;
            out[(long)(nb + 3) * FEAT + col] = x[(long)(nb + 3) * FEAT + col] + v3;
        }
        __syncwarp();
    }
}

// ---------------- launch ----------------
extern "C" void kernel_launch(void* const* d_in, const int* in_sizes, int n_in,
                              void* d_out, int out_size)
{
    const float* x    = (const float*)d_in[0];
    const float* pos  = (const float*)d_in[1];
    const int*   ei   = (const int*)  d_in[2];
    const float* h_w0 = (const float*)d_in[3];
    const float* h_b0 = (const float*)d_in[4];
    const float* h_w1 = (const float*)d_in[5];
    const float* h_b1 = (const float*)d_in[6];
    const float* f_w0 = (const float*)d_in[7];
    const float* f_b0 = (const float*)d_in[8];
    const float* f_w1 = (const float*)d_in[9];
    const float* f_b1 = (const float*)d_in[10];
    const float* g_w0 = (const float*)d_in[11];
    const float* g_b0 = (const float*)d_in[12];
    const float* g_w1 = (const float*)d_in[13];
    const float* g_b1 = (const float*)d_in[14];
    float* out = (float*)d_out;

    const int smem_pre  = (FEAT*HID_H + FEAT*HID + HID_H*3 + HID_H + 4 + HID
                           + 8*FEAT*4 + 8*HID_H*4) * 4;
    const int smem_edge = (3*HID + HID*FEAT + FEAT + 8*HID*EPG) * 4;
    const int smem_post = (FEAT*HID + HID*FEAT + HID + FEAT
                           + 8*FEAT*4 + 8*HID*4) * 4;

    cudaFuncSetAttribute(node_pre_kernel,  cudaFuncAttributeMaxDynamicSharedMemorySize, smem_pre);
    cudaFuncSetAttribute(edge_kernel,      cudaFuncAttributeMaxDynamicSharedMemorySize, smem_edge);
    cudaFuncSetAttribute(node_post_kernel, cudaFuncAttributeMaxDynamicSharedMemorySize, smem_post);

    init_agg_kernel<<<296, 256>>>();
    node_pre_kernel<<<296, 256, smem_pre>>>(x, h_w0, h_b0, h_w1, h_b1, f_w0, f_b0);
    edge_kernel<<<296, 256, smem_edge>>>(pos, ei, f_w0, f_w1, f_b1);
    node_post_kernel<<<148, 256, smem_post>>>(x, g_w0, g_b0, g_w1, g_b1, out);
}

// round 4
// speedup vs baseline: 1.5266x; 1.1698x over previous
#include <cuda_runtime.h>
#include <cuda_bf16.h>

#define N_NODES 50000
#define N_EDGES 800000
#define FEAT 96
#define HID_H 64
#define HID 128
#define TILE 128
#define NTILES (N_EDGES / TILE)     /* 6250 */
#define INIT_ENC 0x007FFFFFu        /* enc(-inf) */

typedef unsigned long long u64;
typedef unsigned u32;

// ---------------- scratch (device globals; no allocs allowed) ----------------
__device__ float    g_delta[N_NODES * 3];
__device__ float    g_xa[N_NODES * HID];
__device__ unsigned g_agg[N_NODES * FEAT];

__device__ __forceinline__ unsigned enc_f(float f) {
    unsigned u = __float_as_uint(f);
    return (u & 0x80000000u) ? ~u : (u | 0x80000000u);
}
__device__ __forceinline__ float dec_f(unsigned k) {
    unsigned u = (k & 0x80000000u) ? (k & 0x7FFFFFFFu) : ~k;
    return __uint_as_float(u);
}

// ---- packed f32x2 helpers ----
__device__ __forceinline__ u64 dup2(float a) {
    u64 r; asm("mov.b64 %0, {%1, %1};" : "=l"(r) : "f"(a)); return r;
}
__device__ __forceinline__ void unpack2(u64 v, float& a, float& b) {
    asm("mov.b64 {%0, %1}, %2;" : "=f"(a), "=f"(b) : "l"(v));
}
__device__ __forceinline__ void fma2(u64& acc, u64 a, u64 b) {
    asm("fma.rn.f32x2 %0, %1, %2, %0;" : "+l"(acc) : "l"(a), "l"(b));
}

__device__ __forceinline__ u32 smem_u32(const void* p) {
    u32 a;
    asm("{ .reg .u64 t; cvta.to.shared.u64 t, %1; cvt.u32.u64 %0, t; }" : "=r"(a) : "l"(p));
    return a;
}

// ---- arch-generic tensor core ops (sm_80+; no 'a'-feature PTX) ----
__device__ __forceinline__ void ldsm_x4(u32* r, u32 addr) {
    asm volatile("ldmatrix.sync.aligned.m8n8.x4.shared.b16 {%0,%1,%2,%3}, [%4];"
        : "=r"(r[0]), "=r"(r[1]), "=r"(r[2]), "=r"(r[3]) : "r"(addr));
}
__device__ __forceinline__ void ldsm_x4_t(u32* r, u32 addr) {
    asm volatile("ldmatrix.sync.aligned.m8n8.x4.trans.shared.b16 {%0,%1,%2,%3}, [%4];"
        : "=r"(r[0]), "=r"(r[1]), "=r"(r[2]), "=r"(r[3]) : "r"(addr));
}
__device__ __forceinline__ void mma_bf16(float* d, const u32* a, const u32* b) {
    asm volatile("mma.sync.aligned.m16n8k16.row.col.f32.bf16.bf16.f32 "
        "{%0,%1,%2,%3}, {%4,%5,%6,%7}, {%8,%9}, {%0,%1,%2,%3};"
        : "+f"(d[0]), "+f"(d[1]), "+f"(d[2]), "+f"(d[3])
        : "r"(a[0]), "r"(a[1]), "r"(a[2]), "r"(a[3]), "r"(b[0]), "r"(b[1]));
}

// split fp32 pair into bf16x2 hi and lo words
__device__ __forceinline__ void split_bf16(float a, float b, u32& hi, u32& lo) {
    __nv_bfloat162 h2 = __floats2bfloat162_rn(a, b);
    float fa = __bfloat162float(__low2bfloat16(h2));
    float fb = __bfloat162float(__high2bfloat16(h2));
    __nv_bfloat162 l2 = __floats2bfloat162_rn(a - fa, b - fb);
    hi = *reinterpret_cast<u32*>(&h2);
    lo = *reinterpret_cast<u32*>(&l2);
}

// ---------------- kernel 0: init agg ----------------
__global__ void init_agg_kernel() {
    int i = blockIdx.x * blockDim.x + threadIdx.x;
    int stride = gridDim.x * blockDim.x;
    for (; i < N_NODES * FEAT; i += stride) g_agg[i] = INIT_ENC;
}

// ---------------- kernel 1: delta = mlp_h(x);  xa = x @ f_w0[3:] + f_b0 ----------------
__global__ __launch_bounds__(256, 2) void node_pre_kernel(
    const float* __restrict__ x,
    const float* __restrict__ h_w0, const float* __restrict__ h_b0,
    const float* __restrict__ h_w1, const float* __restrict__ h_b1,
    const float* __restrict__ f_w0, const float* __restrict__ f_b0)
{
    extern __shared__ float sm[];
    float* s_hw0 = sm;                       // 96*64
    float* s_fw0 = s_hw0 + FEAT * HID_H;     // 96*128
    float* s_hw1 = s_fw0 + FEAT * HID;       // 64*3
    float* s_hb0 = s_hw1 + HID_H * 3;        // 64
    float* s_hb1 = s_hb0 + HID_H;            // 4
    float* s_fb0 = s_hb1 + 4;                // 128
    float* s_x4  = s_fb0 + HID;              // 8*96*4
    float* s_h4  = s_x4 + 8 * FEAT * 4;      // 8*64*4

    int tid = threadIdx.x;
    for (int i = tid; i < FEAT * HID_H; i += 256) s_hw0[i] = h_w0[i];
    for (int i = tid; i < FEAT * HID;   i += 256) s_fw0[i] = f_w0[3 * HID + i];
    for (int i = tid; i < HID_H * 3;    i += 256) s_hw1[i] = h_w1[i];
    if (tid < HID_H) s_hb0[tid] = h_b0[tid];
    if (tid < 3)     s_hb1[tid] = h_b1[tid];
    if (tid < HID)   s_fb0[tid] = f_b0[tid];
    __syncthreads();

    int warp = tid >> 5, lane = tid & 31;
    int warps_total = gridDim.x * 8;
    float* x4 = s_x4 + warp * FEAT * 4;
    float* h4 = s_h4 + warp * HID_H * 4;

    for (int nb = (blockIdx.x * 8 + warp) * 4; nb < N_NODES; nb += warps_total * 4) {
        #pragma unroll
        for (int e = 0; e < 4; e++) {
            const float* xr = x + (long)(nb + e) * FEAT;
            #pragma unroll
            for (int i = 0; i < 3; i++) {
                int k = lane + 32 * i;
                x4[k * 4 + e] = xr[k];
            }
        }
        __syncwarp();

        {
            u64 acc[2][2];
            acc[0][0] = acc[1][0] = dup2(s_hb0[lane]);
            acc[0][1] = acc[1][1] = dup2(s_hb0[lane + 32]);
            #pragma unroll 4
            for (int k = 0; k < FEAT; k++) {
                ulonglong2 xv = *(const ulonglong2*)&x4[k * 4];
                u64 w0 = dup2(s_hw0[k * HID_H + lane]);
                u64 w1 = dup2(s_hw0[k * HID_H + lane + 32]);
                fma2(acc[0][0], xv.x, w0);
                fma2(acc[1][0], xv.y, w0);
                fma2(acc[0][1], xv.x, w1);
                fma2(acc[1][1], xv.y, w1);
            }
            #pragma unroll
            for (int half = 0; half < 2; half++) {
                int j = lane + 32 * half;
                float a, b, c, d;
                unpack2(acc[0][half], a, b);
                unpack2(acc[1][half], c, d);
                *reinterpret_cast<float4*>(&h4[j * 4]) =
                    make_float4(fmaxf(a, 0.f), fmaxf(b, 0.f), fmaxf(c, 0.f), fmaxf(d, 0.f));
            }
        }
        __syncwarp();

        if (lane < 12) {
            int e = lane / 3, c = lane % 3;
            float d = s_hb1[c];
            #pragma unroll 8
            for (int j = 0; j < HID_H; j++)
                d = fmaf(h4[j * 4 + e], s_hw1[j * 3 + c], d);
            g_delta[(nb + e) * 3 + c] = d;
        }

        {
            u64 acc[2][4];
            #pragma unroll
            for (int q = 0; q < 4; q++)
                acc[0][q] = acc[1][q] = dup2(s_fb0[lane + 32 * q]);
            #pragma unroll 4
            for (int k = 0; k < FEAT; k++) {
                ulonglong2 xv = *(const ulonglong2*)&x4[k * 4];
                const float* w = s_fw0 + k * HID;
                #pragma unroll
                for (int q = 0; q < 4; q++) {
                    u64 wq = dup2(w[lane + 32 * q]);
                    fma2(acc[0][q], xv.x, wq);
                    fma2(acc[1][q], xv.y, wq);
                }
            }
            #pragma unroll
            for (int q = 0; q < 4; q++) {
                float v0, v1, v2, v3;
                unpack2(acc[0][q], v0, v1);
                unpack2(acc[1][q], v2, v3);
                int col = lane + 32 * q;
                g_xa[(long)(nb + 0) * HID + col] = v0;
                g_xa[(long)(nb + 1) * HID + col] = v1;
                g_xa[(long)(nb + 2) * HID + col] = v2;
                g_xa[(long)(nb + 3) * HID + col] = v3;
            }
        }
        __syncwarp();
    }
}

// ---------------- kernel 2: edge MLP via mma.sync bf16-split ----------------
// smem byte offsets (all 16B-aligned; row pads chosen for conflict-free ldmatrix)
#define SM_W3   0                       /* 3*128 floats = 1536 */
#define SM_REL  1536                    /* 128*3 floats = 1536 */
#define SM_SRC  3072                    /* 128 ints */
#define SM_DST  3584                    /* 128 ints */
#define SM_BHI  4096                    /* 128 rows * 208B */
#define SM_BLO  (SM_BHI + 26624)
#define SM_AHI  (SM_BLO + 26624)        /* 128 rows * 272B */
#define SM_ALO  (SM_AHI + 34816)
#define SM_EDGE_TOTAL (SM_ALO + 34816)  /* 126976 B */
#define B_PITCH 208
#define A_PITCH 272

__global__ __launch_bounds__(256) void edge_mma_kernel(
    const float* __restrict__ pos,
    const int*   __restrict__ ei,
    const float* __restrict__ f_w0,
    const float* __restrict__ f_w1)
{
    extern __shared__ char smem[];
    u32 sb = smem_u32(smem);
    int tid = threadIdx.x, wid = tid >> 5, lane = tid & 31;

    float* s_w3  = (float*)(smem + SM_W3);
    float* s_rel = (float*)(smem + SM_REL);
    int*   s_src = (int*)(smem + SM_SRC);
    int*   s_dst = (int*)(smem + SM_DST);

    // stage w3 (first 3 rows of f_w0)
    for (int i = tid; i < 3 * HID; i += 256) s_w3[i] = f_w0[i];
    // stage B = w1 [k][n] as bf16 hi/lo, row pitch 208B
    for (int idx = tid; idx < HID * FEAT; idx += 256) {
        int k = idx / FEAT, n = idx % FEAT;
        float v = f_w1[idx];
        __nv_bfloat16 hb = __float2bfloat16(v);
        __nv_bfloat16 lb = __float2bfloat16(v - __bfloat162float(hb));
        *(__nv_bfloat16*)(smem + SM_BHI + k * B_PITCH + n * 2) = hb;
        *(__nv_bfloat16*)(smem + SM_BLO + k * B_PITCH + n * 2) = lb;
    }
    __syncthreads();

    const int e0 = wid * 16;
    const int grp = lane >> 2, q4 = lane & 3;
    // ldmatrix source lane-address components
    const u32 a_row = (u32)(lane & 15);
    const u32 a_col8 = (u32)((lane >> 4) << 3);

    for (int t = blockIdx.x; t < NTILES; t += gridDim.x) {
        // ---- stage edges ----
        if (tid < TILE) {
            int e = tid;
            int gidx = t * TILE + e;
            int s = ei[gidx], d = ei[N_EDGES + gidx];
            s_src[e] = s; s_dst[e] = d;
            #pragma unroll
            for (int c = 0; c < 3; c++)
                s_rel[e * 3 + c] = pos[s * 3 + c] - pos[d * 3 + c] + g_delta[d * 3 + c];
        }
        __syncthreads();

        // ---- phase 1: H[e][j] = relu(rel . w3[:,j] + xa[src][j]) -> bf16 hi/lo ----
        #pragma unroll 2
        for (int ee = 0; ee < 16; ee++) {
            int e = e0 + ee;
            float r0 = s_rel[e * 3 + 0], r1 = s_rel[e * 3 + 1], r2 = s_rel[e * 3 + 2];
            const float2* xap = (const float2*)(g_xa + (long)s_src[e] * HID);
            u32 rowb = (u32)e * A_PITCH;
            #pragma unroll
            for (int p = 0; p < 2; p++) {
                int jw = (p << 5) + lane;               // pair index: j = 2jw, 2jw+1
                float2 xv = __ldg(&xap[jw]);
                float2 wa = *(const float2*)&s_w3[2 * jw];
                float2 wb = *(const float2*)&s_w3[HID + 2 * jw];
                float2 wc = *(const float2*)&s_w3[2 * HID + 2 * jw];
                float h0 = fmaxf(fmaf(r0, wa.x, fmaf(r1, wb.x, fmaf(r2, wc.x, xv.x))), 0.f);
                float h1 = fmaxf(fmaf(r0, wa.y, fmaf(r1, wb.y, fmaf(r2, wc.y, xv.y))), 0.f);
                u32 hi, lo; split_bf16(h0, h1, hi, lo);
                *(u32*)(smem + SM_AHI + rowb + jw * 4) = hi;
                *(u32*)(smem + SM_ALO + rowb + jw * 4) = lo;
            }
        }
        __syncthreads();

        // ---- GEMM: each warp does its 16-edge strip, N=96, K=128, 3-pass split ----
        float acc[12][4];
        #pragma unroll
        for (int n = 0; n < 12; n++)
            acc[n][0] = acc[n][1] = acc[n][2] = acc[n][3] = 0.f;

        #pragma unroll 1
        for (int ks = 0; ks < 8; ks++) {
            u32 k0 = (u32)ks * 16;
            u32 aoff = (u32)(e0 + a_row) * A_PITCH + (k0 + a_col8) * 2;
            u32 ah[4], al[4];
            ldsm_x4(ah, sb + SM_AHI + aoff);
            ldsm_x4(al, sb + SM_ALO + aoff);
            u32 bh[24], bl[24];
            #pragma unroll
            for (int nb = 0; nb < 6; nb++) {
                u32 boff = (k0 + a_row) * B_PITCH + ((u32)nb * 16 + a_col8) * 2;
                ldsm_x4_t(&bh[nb * 4], sb + SM_BHI + boff);
                ldsm_x4_t(&bl[nb * 4], sb + SM_BLO + boff);
            }
            #pragma unroll
            for (int n = 0; n < 12; n++) mma_bf16(acc[n], ah, &bh[2 * n]);
            #pragma unroll
            for (int n = 0; n < 12; n++) mma_bf16(acc[n], al, &bh[2 * n]);
            #pragma unroll
            for (int n = 0; n < 12; n++) mma_bf16(acc[n], ah, &bl[2 * n]);
        }

        // ---- atomics straight from D fragments ----
        {
            int d0 = s_dst[e0 + grp], d1 = s_dst[e0 + grp + 8];
            unsigned* p0 = g_agg + (long)d0 * FEAT;
            unsigned* p1 = g_agg + (long)d1 * FEAT;
            #pragma unroll
            for (int n = 0; n < 12; n++) {
                int col = n * 8 + q4 * 2;
                atomicMax(p0 + col,     enc_f(acc[n][0]));
                atomicMax(p0 + col + 1, enc_f(acc[n][1]));
                atomicMax(p1 + col,     enc_f(acc[n][2]));
                atomicMax(p1 + col + 1, enc_f(acc[n][3]));
            }
        }
        __syncthreads();
    }
}

// ---------------- kernel 3: out = x + mlp_g(decode(agg) + f_b1) ----------------
__global__ __launch_bounds__(512) void node_post_kernel(
    const float* __restrict__ x,
    const float* __restrict__ g_w0, const float* __restrict__ g_b0,
    const float* __restrict__ g_w1, const float* __restrict__ g_b1,
    const float* __restrict__ f_b1,
    float* __restrict__ out)
{
    extern __shared__ float sm[];
    float* s_gw0 = sm;                     // 96*128
    float* s_gw1 = s_gw0 + FEAT * HID;     // 128*96
    float* s_gb0 = s_gw1 + HID * FEAT;     // 128
    float* s_gb1 = s_gb0 + HID;            // 96
    float* s_fb1 = s_gb1 + FEAT;           // 96
    float* s_ag4 = s_fb1 + FEAT;           // 16*96*4
    float* s_h4  = s_ag4 + 16 * FEAT * 4;  // 16*128*4

    int tid = threadIdx.x;
    for (int i = tid; i < FEAT * HID; i += 512) s_gw0[i] = g_w0[i];
    for (int i = tid; i < HID * FEAT; i += 512) s_gw1[i] = g_w1[i];
    if (tid < HID)  s_gb0[tid] = g_b0[tid];
    if (tid < FEAT) s_gb1[tid] = g_b1[tid];
    if (tid >= 128 && tid < 128 + FEAT) s_fb1[tid - 128] = f_b1[tid - 128];
    __syncthreads();

    int warp = tid >> 5, lane = tid & 31;
    int warps_total = gridDim.x * 16;
    float* ag4 = s_ag4 + warp * FEAT * 4;
    float* h4  = s_h4 + warp * HID * 4;

    for (int nb = (blockIdx.x * 16 + warp) * 4; nb < N_NODES; nb += warps_total * 4) {
        #pragma unroll
        for (int e = 0; e < 4; e++) {
            const unsigned* ab = g_agg + (long)(nb + e) * FEAT;
            #pragma unroll
            for (int i = 0; i < 3; i++) {
                int k = lane + 32 * i;
                unsigned kk = ab[k];
                ag4[k * 4 + e] = (kk == INIT_ENC) ? 0.f : dec_f(kk) + s_fb1[k];
            }
        }
        __syncwarp();

        u64 acc[2][4];
        #pragma unroll
        for (int q = 0; q < 4; q++)
            acc[0][q] = acc[1][q] = dup2(s_gb0[lane + 32 * q]);
        #pragma unroll 4
        for (int k = 0; k < FEAT; k++) {
            ulonglong2 av = *(const ulonglong2*)&ag4[k * 4];
            const float* w = s_gw0 + k * HID;
            #pragma unroll
            for (int q = 0; q < 4; q++) {
                u64 wq = dup2(w[lane + 32 * q]);
                fma2(acc[0][q], av.x, wq);
                fma2(acc[1][q], av.y, wq);
            }
        }
        #pragma unroll
        for (int q = 0; q < 4; q++) {
            int j = lane + 32 * q;
            float a, b, c, d;
            unpack2(acc[0][q], a, b);
            unpack2(acc[1][q], c, d);
            *reinterpret_cast<float4*>(&h4[j * 4]) =
                make_float4(fmaxf(a, 0.f), fmaxf(b, 0.f), fmaxf(c, 0.f), fmaxf(d, 0.f));
        }
        __syncwarp();

        u64 acc2[2][3];
        #pragma unroll
        for (int c = 0; c < 3; c++)
            acc2[0][c] = acc2[1][c] = dup2(s_gb1[lane + 32 * c]);
        #pragma unroll 4
        for (int j = 0; j < HID; j++) {
            ulonglong2 hv = *(const ulonglong2*)&h4[j * 4];
            const float* w = s_gw1 + j * FEAT;
            #pragma unroll
            for (int c = 0; c < 3; c++) {
                u64 wc = dup2(w[lane + 32 * c]);
                fma2(acc2[0][c], hv.x, wc);
                fma2(acc2[1][c], hv.y, wc);
            }
        }
        #pragma unroll
        for (int c = 0; c < 3; c++) {
            float v0, v1, v2, v3;
            unpack2(acc2[0][c], v0, v1);
            unpack2(acc2[1][c], v2, v3);
            int col = lane + 32 * c;
            out[(long)(nb + 0) * FEAT + col] = x[(long)(nb + 0) * FEAT + col] + v0;
            out[(long)(nb + 1) * FEAT + col] = x[(long)(nb + 1) * FEAT + col] + v1;
            out[(long)(nb + 2) * FEAT + col] = x[(long)(nb + 2) * FEAT + col] + v2;
            out[(long)(nb + 3) * FEAT + col] = x[(long)(nb + 3) * FEAT + col] + v3;
        }
        __syncwarp();
    }
}

// ---------------- launch ----------------
extern "C" void kernel_launch(void* const* d_in, const int* in_sizes, int n_in,
                              void* d_out, int out_size)
{
    const float* x    = (const float*)d_in[0];
    const float* pos  = (const float*)d_in[1];
    const int*   ei   = (const int*)  d_in[2];
    const float* h_w0 = (const float*)d_in[3];
    const float* h_b0 = (const float*)d_in[4];
    const float* h_w1 = (const float*)d_in[5];
    const float* h_b1 = (const float*)d_in[6];
    const float* f_w0 = (const float*)d_in[7];
    const float* f_b0 = (const float*)d_in[8];
    const float* f_w1 = (const float*)d_in[9];
    const float* f_b1 = (const float*)d_in[10];
    const float* g_w0 = (const float*)d_in[11];
    const float* g_b0 = (const float*)d_in[12];
    const float* g_w1 = (const float*)d_in[13];
    const float* g_b1 = (const float*)d_in[14];
    float* out = (float*)d_out;

    const int smem_pre  = (FEAT*HID_H + FEAT*HID + HID_H*3 + HID_H + 4 + HID
                           + 8*FEAT*4 + 8*HID_H*4) * 4;
    const int smem_post = (FEAT*HID + HID*FEAT + HID + FEAT + FEAT
                           + 16*FEAT*4 + 16*HID*4) * 4;

    cudaFuncSetAttribute(node_pre_kernel,  cudaFuncAttributeMaxDynamicSharedMemorySize, smem_pre);
    cudaFuncSetAttribute(edge_mma_kernel,  cudaFuncAttributeMaxDynamicSharedMemorySize, SM_EDGE_TOTAL);
    cudaFuncSetAttribute(node_post_kernel, cudaFuncAttributeMaxDynamicSharedMemorySize, smem_post);

    init_agg_kernel<<<304, 256>>>();
    node_pre_kernel<<<304, 256, smem_pre>>>(x, h_w0, h_b0, h_w1, h_b1, f_w0, f_b0);
    edge_mma_kernel<<<152, 256, SM_EDGE_TOTAL>>>(pos, ei, f_w0, f_w1);
    node_post_kernel<<<152, 512, smem_post>>>(x, g_w0, g_b0, g_w1, g_b1, f_b1, out);
}